// round 10
// baseline (speedup 1.0000x reference)
#include <cuda_runtime.h>

// ---------------------------------------------------------------------------
// QuantizedActorMLP: x[B,17] -> fq_act -> L1(17->64)+fq_act -> L2(64->64)+fq_act
//                    -> L3(64->6). Exact int8 dots via DP4A.
// Round 10: R9 + (1) coalesced linear smem staging of the input tile
// (conflict-free stride-17 LDS), (2) magic-round requant epilogue (no F2I:
// clamp in float, RNE round via +MAGIC FADD, pack low bytes), (3) FFMA-magic
// input quantization. Dot-product math unchanged.
// ---------------------------------------------------------------------------

#define ACT_SCALE 1.33f
#define QMAXF     127.0f
#define MAGIC     12582912.0f   // 1.5 * 2^23

struct __align__(16) QConst {
    int   W1p[64 * 8];   // [j][g], g<5 real (K padded 17->20), g>=5 zero
    int   W2[64 * 16];   // [j][g]
    int   W3T[16 * 8];   // [jw][k], k<6 real, k>=6 zero
    float b1s[64];       // b1/step
    float b2s[64];       // b2/step
    float b3[8];
    float G1, G2, G3;    // s1, s2, step*s3
};

__device__   QConst gQ;   // staging, written by prep_kernel
__constant__ QConst cQ;   // copied via cudaMemcpyToSymbolAsync

// pack low bytes of 4 words
__device__ __forceinline__ int packq(int q0, int q1, int q2, int q3) {
    return __byte_perm(__byte_perm(q0, q1, 0x0040),
                       __byte_perm(q2, q3, 0x0040), 0x5410);
}

// requant one accumulator -> magic-float whose LOW BYTE is the int8 value.
// Bit-identical to: qi = __float2int_rn(fma(float(acc),G,b)); clamp(qi,+-127).
__device__ __forceinline__ int requant_magic(int acc, float G, float b) {
    float f = fmaf((float)acc, G, b);
    f = fminf(f, QMAXF);
    f = fmaxf(f, -QMAXF);
    float t = __fadd_rn(f, MAGIC);     // RNE integer round; low byte = int8
    return __float_as_int(t);
}

// ---------------------------------------------------------------------------
// Prep: per-tensor max-abs scales + int8 quantize + pack into gQ.
// ---------------------------------------------------------------------------
__global__ void prep_kernel(const float* __restrict__ W1, const float* __restrict__ b1,
                            const float* __restrict__ W2, const float* __restrict__ b2,
                            const float* __restrict__ W3, const float* __restrict__ b3) {
    __shared__ float red[256];
    __shared__ float sS[3];
    const int tid = threadIdx.x;

    const float* Ws[3]  = {W1, W2, W3};
    const int    nel[3] = {64 * 17, 64 * 64, 6 * 64};

    for (int t = 0; t < 3; ++t) {
        float m = 0.0f;
        const float* W = Ws[t];
        for (int i = tid; i < nel[t]; i += 256) m = fmaxf(m, fabsf(W[i]));
        red[tid] = m;
        __syncthreads();
        for (int s = 128; s > 0; s >>= 1) {
            if (tid < s) red[tid] = fmaxf(red[tid], red[tid + s]);
            __syncthreads();
        }
        if (tid == 0) sS[t] = red[0] / QMAXF;
        __syncthreads();
    }

    const float s1 = sS[0], s2 = sS[1], s3 = sS[2];
    const float step = ACT_SCALE / QMAXF;
    if (tid == 0) { gQ.G1 = s1; gQ.G2 = s2; gQ.G3 = step * s3; }
    if (tid < 64) {
        gQ.b1s[tid] = b1[tid] / step;
        gQ.b2s[tid] = b2[tid] / step;
    }
    if (tid < 8) gQ.b3[tid] = (tid < 6) ? b3[tid] : 0.0f;

    // Pack W1 into padded rows of 8 words (g<5 real, K padded 17->20)
    for (int w = tid; w < 64 * 8; w += 256) {
        int j = w >> 3, g = w & 7;
        int word = 0;
        if (g < 5) {
            int q[4];
#pragma unroll
            for (int b = 0; b < 4; ++b) {
                int k = 4 * g + b;
                int v = 0;
                if (k < 17) {
                    float r = rintf(W1[j * 17 + k] / s1);
                    v = (int)fminf(fmaxf(r, -QMAXF), QMAXF);
                }
                q[b] = v;
            }
            word = packq(q[0], q[1], q[2], q[3]);
        }
        gQ.W1p[w] = word;
    }
    // Pack W2: 64 x 64
    for (int w = tid; w < 64 * 16; w += 256) {
        int j = w / 16, g = w % 16;
        int q[4];
#pragma unroll
        for (int b = 0; b < 4; ++b) {
            float r = rintf(W2[j * 64 + 4 * g + b] / s2);
            q[b] = (int)fminf(fmaxf(r, -QMAXF), QMAXF);
        }
        gQ.W2[w] = packq(q[0], q[1], q[2], q[3]);
    }
    // Pack W3 TRANSPOSED: W3T[jw][k] = packed word of W3 row k, cols 4jw..4jw+3
    for (int w = tid; w < 16 * 8; w += 256) {
        int jw = w >> 3, k = w & 7;
        int word = 0;
        if (k < 6) {
            int q[4];
#pragma unroll
            for (int b = 0; b < 4; ++b) {
                float r = rintf(W3[k * 64 + 4 * jw + b] / s3);
                q[b] = (int)fminf(fmaxf(r, -QMAXF), QMAXF);
            }
            word = packq(q[0], q[1], q[2], q[3]);
        }
        gQ.W3T[w] = word;
    }
}

// ---------------------------------------------------------------------------
// Main fused MLP kernel: 256 rows/block, one row per thread, DP4A math,
// weights from the constant bank, input staged linearly in smem (coalesced).
// ---------------------------------------------------------------------------
__global__ __launch_bounds__(256) void mlp_kernel(
    const float* __restrict__ x, float* __restrict__ out, int B) {

    __shared__ float sxf[256 * 17];                 // linear input tile
    __shared__ __align__(16) float sout[256 * 6];

    const int tid  = threadIdx.x;
    const int base = blockIdx.x * 256;
    const int grow = base + tid;
    const int rows = min(256, B - base);

    // ---- coalesced staging: global -> smem (linear, no padding) ----
    {
        const float* xg = x + (size_t)base * 17;
        if (rows == 256) {
            float4* sv = (float4*)sxf;
            const float4* gv = (const float4*)xg;   // base*68 bytes, 16B-aligned
            for (int i = tid; i < 1088; i += 256) sv[i] = gv[i];
        } else {
            const int n = rows * 17;
            for (int i = tid; i < n; i += 256) sxf[i] = xg[i];
        }
    }
    __syncthreads();

    if (grow < B) {
        const float INV = QMAXF / ACT_SCALE;
        const float G1 = cQ.G1, G2 = cQ.G2, G3 = cQ.G3;
        const int   MZ = 0x4B400000;                // float bits of MAGIC (low byte 0)

        // ---- own row: 17 conflict-free LDS, FFMA-magic quant, pack ----
        int p0[5];
        {
            const float* xr = sxf + tid * 17;       // stride 17 coprime w/ 32 banks
            int q[17];
#pragma unroll
            for (int k = 0; k < 17; ++k) {
                float v = xr[k];
                v = fminf(fmaxf(v, -ACT_SCALE), ACT_SCALE);
                float t = fmaf(v, INV, MAGIC);      // RNE round; low byte = int8
                q[k] = __float_as_int(t);
            }
#pragma unroll
            for (int g = 0; g < 4; ++g)
                p0[g] = packq(q[4 * g], q[4 * g + 1], q[4 * g + 2], q[4 * g + 3]);
            p0[4] = packq(q[16], MZ, MZ, MZ);
        }

        // ---- layer 1: 17 -> 64, magic requant, pack ----
        int a1[16];
#pragma unroll
        for (int jw = 0; jw < 16; ++jw) {
            const float4 bb = *(const float4*)&cQ.b1s[jw * 4];
            const float bj[4] = {bb.x, bb.y, bb.z, bb.w};
            int q[4];
#pragma unroll
            for (int jj = 0; jj < 4; ++jj) {
                const int j = jw * 4 + jj;
                const int4 wv = *(const int4*)&cQ.W1p[j * 8];
                const int  w4 = cQ.W1p[j * 8 + 4];
                int acc = 0;
                acc = __dp4a(p0[0], wv.x, acc);
                acc = __dp4a(p0[1], wv.y, acc);
                acc = __dp4a(p0[2], wv.z, acc);
                acc = __dp4a(p0[3], wv.w, acc);
                acc = __dp4a(p0[4], w4,   acc);
                q[jj] = requant_magic(acc, G1, bj[jj]);
            }
            a1[jw] = packq(q[0], q[1], q[2], q[3]);
        }

        // ---- layer 2 (64 -> 64, magic requant) fused with layer-3 accumulation ----
        int acc3[6] = {0, 0, 0, 0, 0, 0};
#pragma unroll
        for (int jw = 0; jw < 16; ++jw) {
            const float4 bb = *(const float4*)&cQ.b2s[jw * 4];
            const float bj[4] = {bb.x, bb.y, bb.z, bb.w};
            int q[4];
#pragma unroll
            for (int jj = 0; jj < 4; ++jj) {
                const int j = jw * 4 + jj;
                int acc = 0;
#pragma unroll
                for (int g = 0; g < 4; ++g) {
                    const int4 w = *(const int4*)&cQ.W2[j * 16 + g * 4];
                    acc = __dp4a(a1[g * 4 + 0], w.x, acc);
                    acc = __dp4a(a1[g * 4 + 1], w.y, acc);
                    acc = __dp4a(a1[g * 4 + 2], w.z, acc);
                    acc = __dp4a(a1[g * 4 + 3], w.w, acc);
                }
                q[jj] = requant_magic(acc, G2, bj[jj]);
            }
            const int a2w = packq(q[0], q[1], q[2], q[3]);
            // transposed W3: 2 vector loads per jw
            const int4 w3lo = *(const int4*)&cQ.W3T[jw * 8];
            const int2 w3hi = *(const int2*)&cQ.W3T[jw * 8 + 4];
            acc3[0] = __dp4a(a2w, w3lo.x, acc3[0]);
            acc3[1] = __dp4a(a2w, w3lo.y, acc3[1]);
            acc3[2] = __dp4a(a2w, w3lo.z, acc3[2]);
            acc3[3] = __dp4a(a2w, w3lo.w, acc3[3]);
            acc3[4] = __dp4a(a2w, w3hi.x, acc3[4]);
            acc3[5] = __dp4a(a2w, w3hi.y, acc3[5]);
        }

        // ---- layer 3 epilogue into smem staging ----
#pragma unroll
        for (int k = 0; k < 6; ++k)
            sout[tid * 6 + k] = fmaf((float)acc3[k], G3, cQ.b3[k]);
    }
    __syncthreads();

    // ---- coalesced output store ----
    float* og = out + (size_t)base * 6;
    if (rows == 256) {
        float4* ov = (float4*)og;
        const float4* sv = (const float4*)sout;
        for (int i = tid; i < 384; i += 256) ov[i] = sv[i];
    } else {
        const int nf = rows * 6;
        for (int i = tid; i < nf; i += 256) og[i] = sout[i];
    }
}

extern "C" void kernel_launch(void* const* d_in, const int* in_sizes, int n_in,
                              void* d_out, int out_size) {
    const float* x  = (const float*)d_in[0];
    const float* W1 = (const float*)d_in[1];
    const float* b1 = (const float*)d_in[2];
    const float* W2 = (const float*)d_in[3];
    const float* b2 = (const float*)d_in[4];
    const float* W3 = (const float*)d_in[5];
    const float* b3 = (const float*)d_in[6];
    float* out = (float*)d_out;

    const int B = in_sizes[0] / 17;
    const int blocks = (B + 255) / 256;

    prep_kernel<<<1, 256>>>(W1, b1, W2, b2, W3, b3);

    void* gq_ptr = nullptr;
    cudaGetSymbolAddress(&gq_ptr, gQ);
    cudaMemcpyToSymbolAsync(cQ, gq_ptr, sizeof(QConst), 0,
                            cudaMemcpyDeviceToDevice, 0);

    mlp_kernel<<<blocks, 256>>>(x, out, B);
}

// round 11
// speedup vs baseline: 1.0308x; 1.0308x over previous
#include <cuda_runtime.h>

// ---------------------------------------------------------------------------
// QuantizedActorMLP: x[B,17] -> fq_act -> L1(17->64)+fq_act -> L2(64->64)+fq_act
//                    -> L3(64->6). Exact int8 dots via DP4A.
// Round 11: Round-2 base (measured best: scalar W1/W3 -> LDCU uniform path,
// vector W2 -> const port under budget) + CVT-port relief: all fake-quant
// rounds done with FADD-magic (low byte of float bits = int8), no F2I in the
// hot path. Boundary-equivalent to R2's round-then-clamp (proven in R10).
// ---------------------------------------------------------------------------

#define ACT_SCALE 1.33f
#define QMAXF     127.0f
#define MAGIC     12582912.0f   // 1.5 * 2^23

struct QConst {
    int   W1[64 * 5];    // [j][g] : W1 row j, inputs 4g..4g+3 (k>=17 padded 0)
    int   W2[64 * 16];   // [j][g]
    int   W3[6 * 16];    // [k][g]
    float b1s[64];       // b1/step
    float b2s[64];       // b2/step
    float b3[8];
    float G1, G2, G3;    // s1, s2, step*s3
};

__device__   QConst gQ;   // staging, written by prep_kernel
__constant__ QConst cQ;   // copied via cudaMemcpyToSymbolAsync

__device__ __forceinline__ int packq(int q0, int q1, int q2, int q3) {
    return __byte_perm(__byte_perm(q0, q1, 0x0040),
                       __byte_perm(q2, q3, 0x0040), 0x5410);
}

// requant one accumulator -> word whose LOW BYTE is the int8 value.
// Equivalent to: qi = __float2int_rn(fma(float(acc),G,b)); clamp(qi,+-127).
__device__ __forceinline__ int requant_magic(int acc, float G, float b) {
    float f = fmaf((float)acc, G, b);
    f = fminf(f, QMAXF);
    f = fmaxf(f, -QMAXF);
    float t = __fadd_rn(f, MAGIC);     // RNE integer round; low byte = int8
    return __float_as_int(t);
}

// ---------------------------------------------------------------------------
// Prep: per-tensor max-abs scales + int8 quantize + pack into gQ.
// ---------------------------------------------------------------------------
__global__ void prep_kernel(const float* __restrict__ W1, const float* __restrict__ b1,
                            const float* __restrict__ W2, const float* __restrict__ b2,
                            const float* __restrict__ W3, const float* __restrict__ b3) {
    __shared__ float red[256];
    __shared__ float sS[3];
    const int tid = threadIdx.x;

    const float* Ws[3]  = {W1, W2, W3};
    const int    nel[3] = {64 * 17, 64 * 64, 6 * 64};

    for (int t = 0; t < 3; ++t) {
        float m = 0.0f;
        const float* W = Ws[t];
        for (int i = tid; i < nel[t]; i += 256) m = fmaxf(m, fabsf(W[i]));
        red[tid] = m;
        __syncthreads();
        for (int s = 128; s > 0; s >>= 1) {
            if (tid < s) red[tid] = fmaxf(red[tid], red[tid + s]);
            __syncthreads();
        }
        if (tid == 0) sS[t] = red[0] / QMAXF;
        __syncthreads();
    }

    const float s1 = sS[0], s2 = sS[1], s3 = sS[2];
    const float step = ACT_SCALE / QMAXF;
    if (tid == 0) {
        gQ.G1 = s1;
        gQ.G2 = s2;
        gQ.G3 = step * s3;
    }
    if (tid < 64) {
        gQ.b1s[tid] = b1[tid] / step;
        gQ.b2s[tid] = b2[tid] / step;
    }
    if (tid < 8) gQ.b3[tid] = (tid < 6) ? b3[tid] : 0.0f;

    // Pack W1: 64 rows x 17 (pad to 20)
    for (int w = tid; w < 64 * 5; w += 256) {
        int j = w / 5, g = w % 5;
        int q[4];
#pragma unroll
        for (int b = 0; b < 4; ++b) {
            int k = 4 * g + b;
            int v = 0;
            if (k < 17) {
                float r = rintf(W1[j * 17 + k] / s1);
                v = (int)fminf(fmaxf(r, -QMAXF), QMAXF);
            }
            q[b] = v;
        }
        gQ.W1[w] = packq(q[0], q[1], q[2], q[3]);
    }
    // Pack W2: 64 x 64
    for (int w = tid; w < 64 * 16; w += 256) {
        int j = w / 16, g = w % 16;
        int q[4];
#pragma unroll
        for (int b = 0; b < 4; ++b) {
            float r = rintf(W2[j * 64 + 4 * g + b] / s2);
            q[b] = (int)fminf(fmaxf(r, -QMAXF), QMAXF);
        }
        gQ.W2[w] = packq(q[0], q[1], q[2], q[3]);
    }
    // Pack W3: 6 x 64
    for (int w = tid; w < 6 * 16; w += 256) {
        int k = w / 16, g = w % 16;
        int q[4];
#pragma unroll
        for (int b = 0; b < 4; ++b) {
            float r = rintf(W3[k * 64 + 4 * g + b] / s3);
            q[b] = (int)fminf(fmaxf(r, -QMAXF), QMAXF);
        }
        gQ.W3[w] = packq(q[0], q[1], q[2], q[3]);
    }
}

// ---------------------------------------------------------------------------
// Main fused MLP kernel: 256 rows/block, one row per thread, DP4A math,
// weights from constant bank (R2 layout), CVT-free fake-quant rounds.
// ---------------------------------------------------------------------------
__global__ __launch_bounds__(256) void mlp_kernel(
    const float* __restrict__ x, float* __restrict__ out, int B) {

    __shared__ __align__(16) unsigned char sxq[256 * 20];  // packed int8 rows
    __shared__ __align__(16) float sout[256 * 6];

    const int tid  = threadIdx.x;
    const int base = blockIdx.x * 256;
    const int rows = min(256, B - base);

    const float INV = QMAXF / ACT_SCALE;

    // Zero pad region (covers K 17..19 and tail rows), then quantize+store bytes.
    for (int i = tid; i < 1280; i += 256) ((int*)sxq)[i] = 0;
    __syncthreads();
    {
        const float* xg = x + (size_t)base * 17;
        const int n = rows * 17;
        for (int i = tid; i < n; i += 256) {
            float v = xg[i];
            v = fminf(fmaxf(v, -ACT_SCALE), ACT_SCALE);
            float t = fmaf(v, INV, MAGIC);         // RNE round; low byte = int8
            int r = i / 17;
            int k = i - r * 17;
            sxq[r * 20 + k] = (unsigned char)__float_as_int(t);
        }
    }
    __syncthreads();

    if (tid < rows) {
        const float G1 = cQ.G1, G2 = cQ.G2, G3 = cQ.G3;

        int p0[5];
        {
            const int* rp = (const int*)(sxq + tid * 20);
#pragma unroll
            for (int g = 0; g < 5; ++g) p0[g] = rp[g];
        }

        // ---- layer 1: 17 -> 64, magic requant, pack ----
        int a1[16];
#pragma unroll
        for (int jw = 0; jw < 16; ++jw) {
            const float4 bb = *(const float4*)&cQ.b1s[jw * 4];
            const float bj[4] = {bb.x, bb.y, bb.z, bb.w};
            int q[4];
#pragma unroll
            for (int jj = 0; jj < 4; ++jj) {
                const int j = jw * 4 + jj;
                int acc = 0;
#pragma unroll
                for (int g = 0; g < 5; ++g) acc = __dp4a(p0[g], cQ.W1[j * 5 + g], acc);
                q[jj] = requant_magic(acc, G1, bj[jj]);
            }
            a1[jw] = packq(q[0], q[1], q[2], q[3]);
        }

        // ---- layer 2 (64 -> 64, magic requant) fused with layer-3 accumulation ----
        int acc3[6] = {0, 0, 0, 0, 0, 0};
#pragma unroll
        for (int jw = 0; jw < 16; ++jw) {
            const float4 bb = *(const float4*)&cQ.b2s[jw * 4];
            const float bj[4] = {bb.x, bb.y, bb.z, bb.w};
            int q[4];
#pragma unroll
            for (int jj = 0; jj < 4; ++jj) {
                const int j = jw * 4 + jj;
                int acc = 0;
#pragma unroll
                for (int g = 0; g < 4; ++g) {
                    const int4 w = *(const int4*)&cQ.W2[j * 16 + g * 4];
                    acc = __dp4a(a1[g * 4 + 0], w.x, acc);
                    acc = __dp4a(a1[g * 4 + 1], w.y, acc);
                    acc = __dp4a(a1[g * 4 + 2], w.z, acc);
                    acc = __dp4a(a1[g * 4 + 3], w.w, acc);
                }
                q[jj] = requant_magic(acc, G2, bj[jj]);
            }
            const int a2w = packq(q[0], q[1], q[2], q[3]);
#pragma unroll
            for (int k = 0; k < 6; ++k)
                acc3[k] = __dp4a(a2w, cQ.W3[k * 16 + jw], acc3[k]);
        }

        // ---- layer 3 epilogue ----
#pragma unroll
        for (int k = 0; k < 6; ++k)
            sout[tid * 6 + k] = fmaf((float)acc3[k], G3, cQ.b3[k]);
    }
    __syncthreads();

    // Coalesced output store
    float* og = out + (size_t)base * 6;
    if (rows == 256) {
        float4* ov = (float4*)og;
        const float4* sv = (const float4*)sout;
        for (int i = tid; i < 384; i += 256) ov[i] = sv[i];
    } else {
        const int nf = rows * 6;
        for (int i = tid; i < nf; i += 256) og[i] = sout[i];
    }
}

extern "C" void kernel_launch(void* const* d_in, const int* in_sizes, int n_in,
                              void* d_out, int out_size) {
    const float* x  = (const float*)d_in[0];
    const float* W1 = (const float*)d_in[1];
    const float* b1 = (const float*)d_in[2];
    const float* W2 = (const float*)d_in[3];
    const float* b2 = (const float*)d_in[4];
    const float* W3 = (const float*)d_in[5];
    const float* b3 = (const float*)d_in[6];
    float* out = (float*)d_out;

    const int B = in_sizes[0] / 17;
    const int blocks = (B + 255) / 256;

    prep_kernel<<<1, 256>>>(W1, b1, W2, b2, W3, b3);

    void* gq_ptr = nullptr;
    cudaGetSymbolAddress(&gq_ptr, gQ);
    cudaMemcpyToSymbolAsync(cQ, gq_ptr, sizeof(QConst), 0,
                            cudaMemcpyDeviceToDevice, 0);

    mlp_kernel<<<blocks, 256>>>(x, out, B);
}